// round 1
// baseline (speedup 1.0000x reference)
#include <cuda_runtime.h>
#include <cuda_bf16.h>
#include <cstdio>

// ---------------------------------------------------------------------------
// Problem constants
// ---------------------------------------------------------------------------
#define H 64
#define NNODES 40000
#define NE 60000
#define NC5 30000
#define NC6 25000
#define E_ROWS (2 * NE)      // 120000
#define C5_ROWS (5 * NC5)    // 150000
#define C6_ROWS (6 * NC6)    // 150000
#define EPS 1e-5f

// ---------------------------------------------------------------------------
// Device scratch (static: no allocation allowed)
// ---------------------------------------------------------------------------
__device__ float g_node64[NNODES * 64];        // node accumulator, 64 ch
__device__ float g_node128[NNODES * 128];      // node accumulator, 128 ch
__device__ float g_nodeS[NNODES * 320];        // summed node accumulator, 320 ch
__device__ float g_tmp128[C5_ROWS * 128];      // first-gather output (reused for c6)
__device__ float g_new5[C5_ROWS * 320];        // cycle5 MLP input
__device__ float g_new6[C6_ROWS * 320];        // cycle6 MLP input
__device__ float g_xE[E_ROWS * 704];           // edge MLP input
__device__ float g_h[C5_ROWS * 128];           // GEMM1 output (reused per MLP)
__device__ float g_z[C5_ROWS * 64];            // GEMM2 output pre-BN (reused)
__device__ float g_sum[128];
__device__ float g_sq[128];
__device__ float g_scale1[128];
__device__ float g_shift1[128];
__device__ float g_scale2[64];
__device__ float g_shift2[64];

// ---------------------------------------------------------------------------
// Utility kernels
// ---------------------------------------------------------------------------
__global__ void zero_kernel(float* __restrict__ p, size_t n) {
    size_t i = (size_t)blockIdx.x * blockDim.x + threadIdx.x;
    if (i < n) p[i] = 0.f;
}

// scatter-add rows of src[rows, C] into node[atoms[r], C] (float4 per thread)
__global__ void scatter_add4(const float* __restrict__ src,
                             const int* __restrict__ atoms,
                             float* __restrict__ node, int rows, int C) {
    int C4 = C >> 2;
    int idx = blockIdx.x * blockDim.x + threadIdx.x;
    int total = rows * C4;
    if (idx >= total) return;
    int r = idx / C4;
    int c = (idx - r * C4) << 2;
    float4 v = *reinterpret_cast<const float4*>(&src[(size_t)r * C + c]);
    float* dst = &node[(size_t)atoms[r] * C + c];
    atomicAdd(dst + 0, v.x);
    atomicAdd(dst + 1, v.y);
    atomicAdd(dst + 2, v.z);
    atomicAdd(dst + 3, v.w);
}

// For each cycle i (G contiguous rows), channel c:
//   v[k] = node[atoms[i*G+k], c]; bc = sum_k v[k]
//   out[(i*G+k)*pitch + c]     = v[k]   (local)
//   out[(i*G+k)*pitch + C + c] = bc     (broadcast)
template <int G>
__global__ void gather_lb(const float* __restrict__ node,
                          const int* __restrict__ atoms,
                          float* __restrict__ out, int nCyc, int C, int pitch) {
    int idx = blockIdx.x * blockDim.x + threadIdx.x;
    if (idx >= nCyc * C) return;
    int i = idx / C;
    int c = idx - i * C;
    int base = i * G;
    float v[G];
    float bc = 0.f;
#pragma unroll
    for (int k = 0; k < G; k++) {
        int a = atoms[base + k];
        v[k] = node[(size_t)a * C + c];
        bc += v[k];
    }
#pragma unroll
    for (int k = 0; k < G; k++) {
        size_t o = (size_t)(base + k) * pitch;
        out[o + c] = v[k];
        out[o + C + c] = bc;
    }
}

// copy 64-channel feats into dst[:, off:off+64] with row pitch
__global__ void copy_off(const float* __restrict__ src, float* __restrict__ dst,
                         int rows, int pitch, int off) {
    int idx = blockIdx.x * blockDim.x + threadIdx.x;
    if (idx >= rows * 64) return;
    int r = idx >> 6;
    int c = idx & 63;
    dst[(size_t)r * pitch + off + c] = src[idx];
}

// edge gather: xE[r] = [feats(0:64, filled separately) | local(64:384) | bc(384:704)]
__global__ void gather_edge(const float* __restrict__ nodeS,
                            const int* __restrict__ atoms,
                            float* __restrict__ xE, int nE) {
    int idx = blockIdx.x * blockDim.x + threadIdx.x;
    if (idx >= nE * 320) return;
    int e = idx / 320;
    int c = idx - e * 320;
    int a0 = atoms[2 * e];
    int a1 = atoms[2 * e + 1];
    float v0 = nodeS[(size_t)a0 * 320 + c];
    float v1 = nodeS[(size_t)a1 * 320 + c];
    float bc = v0 + v1;
    size_t r0 = (size_t)(2 * e) * 704;
    size_t r1 = (size_t)(2 * e + 1) * 704;
    xE[r0 + 64 + c] = v0;
    xE[r0 + 384 + c] = bc;
    xE[r1 + 64 + c] = v1;
    xE[r1 + 384 + c] = bc;
}

__global__ void make_scaleshift(const float* __restrict__ sum_,
                                const float* __restrict__ sq_,
                                const float* __restrict__ g,
                                const float* __restrict__ b,
                                float* __restrict__ scale,
                                float* __restrict__ shift, int C, float invM) {
    int j = blockIdx.x * blockDim.x + threadIdx.x;
    if (j >= C) return;
    float m = sum_[j] * invM;
    float v = sq_[j] * invM - m * m;
    v = fmaxf(v, 0.f);
    float s = g[j] * rsqrtf(v + EPS);
    scale[j] = s;
    shift[j] = b[j] - m * s;
}

__global__ void bn_relu_out(const float* __restrict__ z,
                            const float* __restrict__ scale,
                            const float* __restrict__ shift,
                            float* __restrict__ out, size_t n, int C) {
    size_t idx = (size_t)blockIdx.x * blockDim.x + threadIdx.x;
    if (idx >= n) return;
    int c = (int)(idx % C);
    out[idx] = fmaxf(z[idx] * scale[c] + shift[c], 0.f);
}

// ---------------------------------------------------------------------------
// Tiled fp32 GEMM with fused BN-stats epilogue, optional fused input BN+ReLU.
// A: [M,K] row-major, B: [K,N] row-major, C: [M,N].
// colSum/colSq accumulate per-column sum / sum-of-squares of C (valid rows only).
// APPLY_IN: a' = relu(a*inScale[k] + inShift[k]) on A-tile load.
// K must be divisible by BK; N divisible by BN (grid.x covers N).
// ---------------------------------------------------------------------------
template <int BM, int BN, int BK, int TM, int TN, bool APPLY_IN>
__global__ void __launch_bounds__((BM / TM) * (BN / TN))
gemm_bn_stats(const float* __restrict__ A, const float* __restrict__ B,
              float* __restrict__ C, int M, int K, int N,
              const float* __restrict__ inScale,
              const float* __restrict__ inShift,
              float* __restrict__ colSum, float* __restrict__ colSq) {
    constexpr int NT = (BM / TM) * (BN / TN);
    constexpr int SMEM_MAIN = BK * (BM + BN);
    constexpr int SMEM_STAT = 2 * (BM / TM) * BN;
    constexpr int SMEM_SZ = SMEM_MAIN > SMEM_STAT ? SMEM_MAIN : SMEM_STAT;
    __shared__ float smem[SMEM_SZ];
    float* As = smem;              // [BK][BM] (transposed)
    float* Bs = smem + BK * BM;    // [BK][BN]

    const int tid = threadIdx.x;
    const int mBase = blockIdx.y * BM;
    const int nBase = blockIdx.x * BN;
    const int ty = tid / (BN / TN);
    const int tx = tid % (BN / TN);

    float acc[TM][TN];
#pragma unroll
    for (int i = 0; i < TM; i++)
#pragma unroll
        for (int j = 0; j < TN; j++) acc[i][j] = 0.f;

    for (int k0 = 0; k0 < K; k0 += BK) {
        // load A tile (zero-pad OOB rows)
        for (int v = tid; v < BM * BK / 4; v += NT) {
            int row = v / (BK / 4);
            int kc = (v % (BK / 4)) * 4;
            int gr = mBase + row;
            float4 a = make_float4(0.f, 0.f, 0.f, 0.f);
            if (gr < M)
                a = *reinterpret_cast<const float4*>(&A[(size_t)gr * K + k0 + kc]);
            if (APPLY_IN) {
                int kg = k0 + kc;
                a.x = fmaxf(a.x * inScale[kg + 0] + inShift[kg + 0], 0.f);
                a.y = fmaxf(a.y * inScale[kg + 1] + inShift[kg + 1], 0.f);
                a.z = fmaxf(a.z * inScale[kg + 2] + inShift[kg + 2], 0.f);
                a.w = fmaxf(a.w * inScale[kg + 3] + inShift[kg + 3], 0.f);
            }
            As[(kc + 0) * BM + row] = a.x;
            As[(kc + 1) * BM + row] = a.y;
            As[(kc + 2) * BM + row] = a.z;
            As[(kc + 3) * BM + row] = a.w;
        }
        // load B tile
        for (int v = tid; v < BK * BN / 4; v += NT) {
            int row = v / (BN / 4);
            int col = (v % (BN / 4)) * 4;
            *reinterpret_cast<float4*>(&Bs[row * BN + col]) =
                *reinterpret_cast<const float4*>(
                    &B[(size_t)(k0 + row) * N + nBase + col]);
        }
        __syncthreads();
#pragma unroll
        for (int kk = 0; kk < BK; kk++) {
            float rm[TM], rn[TN];
#pragma unroll
            for (int i = 0; i < TM; i++) rm[i] = As[kk * BM + ty * TM + i];
#pragma unroll
            for (int j = 0; j < TN; j++) rn[j] = Bs[kk * BN + tx * TN + j];
#pragma unroll
            for (int i = 0; i < TM; i++)
#pragma unroll
                for (int j = 0; j < TN; j++) acc[i][j] += rm[i] * rn[j];
        }
        __syncthreads();
    }

    // store C (vectorized), guarded by M
#pragma unroll
    for (int i = 0; i < TM; i++) {
        int gr = mBase + ty * TM + i;
        if (gr < M) {
#pragma unroll
            for (int j = 0; j < TN; j += 4) {
                float4 o = make_float4(acc[i][j], acc[i][j + 1], acc[i][j + 2],
                                       acc[i][j + 3]);
                *reinterpret_cast<float4*>(
                    &C[(size_t)gr * N + nBase + tx * TN + j]) = o;
            }
        }
    }

    // fused BN stats: per-thread partial column sums over valid rows
    float ps[TN], pq[TN];
#pragma unroll
    for (int j = 0; j < TN; j++) { ps[j] = 0.f; pq[j] = 0.f; }
#pragma unroll
    for (int i = 0; i < TM; i++) {
        int gr = mBase + ty * TM + i;
        if (gr < M) {
#pragma unroll
            for (int j = 0; j < TN; j++) {
                float v = acc[i][j];
                ps[j] += v;
                pq[j] += v * v;
            }
        }
    }
    __syncthreads();  // smem tile space no longer needed
    float* sSum = smem;
    float* sSq = smem + (BM / TM) * BN;
#pragma unroll
    for (int j = 0; j < TN; j++) {
        sSum[ty * BN + tx * TN + j] = ps[j];
        sSq[ty * BN + tx * TN + j] = pq[j];
    }
    __syncthreads();
    if (tid < BN) {
        float s = 0.f, q = 0.f;
#pragma unroll
        for (int t = 0; t < BM / TM; t++) {
            s += sSum[t * BN + tid];
            q += sSq[t * BN + tid];
        }
        atomicAdd(&colSum[nBase + tid], s);
        atomicAdd(&colSq[nBase + tid], q);
    }
}

// ---------------------------------------------------------------------------
// Host orchestration
// ---------------------------------------------------------------------------
static inline int cdiv(int a, int b) { return (a + b - 1) / b; }

static float* sym_addr(const void* s) {
    void* p = nullptr;
    cudaGetSymbolAddress(&p, s);
    return (float*)p;
}

static void run_mlp(const float* X, int M, int K, const float* W1,
                    const float* g1, const float* b1, const float* W2,
                    const float* g2, const float* b2, float* h, float* z,
                    float* out, float* psum, float* psq, float* sc1,
                    float* sh1, float* sc2, float* sh2) {
    zero_kernel<<<1, 256>>>(psum, 128);
    zero_kernel<<<1, 256>>>(psq, 128);
    gemm_bn_stats<128, 128, 8, 8, 8, false>
        <<<dim3(1, cdiv(M, 128)), 256>>>(X, W1, h, M, K, 128, nullptr, nullptr,
                                         psum, psq);
    make_scaleshift<<<1, 128>>>(psum, psq, g1, b1, sc1, sh1, 128, 1.f / M);
    zero_kernel<<<1, 256>>>(psum, 128);
    zero_kernel<<<1, 256>>>(psq, 128);
    gemm_bn_stats<128, 64, 16, 8, 4, true>
        <<<dim3(1, cdiv(M, 128)), 256>>>(h, W2, z, M, 128, 64, sc1, sh1, psum,
                                         psq);
    make_scaleshift<<<1, 64>>>(psum, psq, g2, b2, sc2, sh2, 64, 1.f / M);
    size_t n = (size_t)M * 64;
    bn_relu_out<<<(int)((n + 255) / 256), 256>>>(z, sc2, sh2, out, n, 64);
}

extern "C" void kernel_launch(void* const* d_in, const int* in_sizes, int n_in,
                              void* d_out, int out_size) {
    const float* edge_feats = (const float*)d_in[0];
    const float* c5_feats = (const float*)d_in[1];
    const float* c6_feats = (const float*)d_in[2];
    const int* e_atoms = (const int*)d_in[3];
    const int* c5_atoms = (const int*)d_in[4];
    const int* c6_atoms = (const int*)d_in[5];
    const float* eW1 = (const float*)d_in[6];
    const float* eg1 = (const float*)d_in[7];
    const float* eb1 = (const float*)d_in[8];
    const float* eW2 = (const float*)d_in[9];
    const float* eg2 = (const float*)d_in[10];
    const float* eb2 = (const float*)d_in[11];
    const float* cW1 = (const float*)d_in[12];
    const float* cg1 = (const float*)d_in[13];
    const float* cb1 = (const float*)d_in[14];
    const float* cW2 = (const float*)d_in[15];
    const float* cg2 = (const float*)d_in[16];
    const float* cb2 = (const float*)d_in[17];

    float* out_edge = (float*)d_out;
    float* out_c5 = out_edge + (size_t)E_ROWS * H;
    float* out_c6 = out_c5 + (size_t)C5_ROWS * H;

    float* node64 = sym_addr(g_node64);
    float* node128 = sym_addr(g_node128);
    float* nodeS = sym_addr(g_nodeS);
    float* tmp128 = sym_addr(g_tmp128);
    float* new5 = sym_addr(g_new5);
    float* new6 = sym_addr(g_new6);
    float* xE = sym_addr(g_xE);
    float* h = sym_addr(g_h);
    float* z = sym_addr(g_z);
    float* psum = sym_addr(g_sum);
    float* psq = sym_addr(g_sq);
    float* sc1 = sym_addr(g_scale1);
    float* sh1 = sym_addr(g_shift1);
    float* sc2 = sym_addr(g_scale2);
    float* sh2 = sym_addr(g_shift2);

    const int TB = 256;

    // --- node1 = segsum(edge_feats by edge_atoms), 64 ch ---
    zero_kernel<<<cdiv(NNODES * 64, TB), TB>>>(node64, (size_t)NNODES * 64);
    scatter_add4<<<cdiv(E_ROWS * 64 / 4, TB), TB>>>(edge_feats, e_atoms,
                                                    node64, E_ROWS, 64);

    // --- cycle5 chain: gather1 -> scatter -> gather2 -> new5 ---
    gather_lb<5><<<cdiv(NC5 * 64, TB), TB>>>(node64, c5_atoms, tmp128, NC5, 64,
                                             128);
    zero_kernel<<<cdiv(NNODES * 128, TB), TB>>>(node128, (size_t)NNODES * 128);
    scatter_add4<<<cdiv(C5_ROWS * 128 / 4, TB), TB>>>(tmp128, c5_atoms,
                                                      node128, C5_ROWS, 128);
    gather_lb<5><<<cdiv(NC5 * 128, TB), TB>>>(node128, c5_atoms, new5, NC5,
                                              128, 320);
    copy_off<<<cdiv(C5_ROWS * 64, TB), TB>>>(c5_feats, new5, C5_ROWS, 320, 256);

    // --- cycle6 chain ---
    gather_lb<6><<<cdiv(NC6 * 64, TB), TB>>>(node64, c6_atoms, tmp128, NC6, 64,
                                             128);
    zero_kernel<<<cdiv(NNODES * 128, TB), TB>>>(node128, (size_t)NNODES * 128);
    scatter_add4<<<cdiv(C6_ROWS * 128 / 4, TB), TB>>>(tmp128, c6_atoms,
                                                      node128, C6_ROWS, 128);
    gather_lb<6><<<cdiv(NC6 * 128, TB), TB>>>(node128, c6_atoms, new6, NC6,
                                              128, 320);
    copy_off<<<cdiv(C6_ROWS * 64, TB), TB>>>(c6_feats, new6, C6_ROWS, 320, 256);

    // --- nodeS = segsum(new5 by c5_atoms) + segsum(new6 by c6_atoms), 320 ch ---
    zero_kernel<<<cdiv(NNODES * 320, TB), TB>>>(nodeS, (size_t)NNODES * 320);
    scatter_add4<<<cdiv(C5_ROWS * 320 / 4, TB), TB>>>(new5, c5_atoms, nodeS,
                                                      C5_ROWS, 320);
    scatter_add4<<<cdiv(C6_ROWS * 320 / 4, TB), TB>>>(new6, c6_atoms, nodeS,
                                                      C6_ROWS, 320);

    // --- edge MLP input: xE = [edge_feats | local | bc] (704 ch) ---
    gather_edge<<<cdiv(NE * 320, TB), TB>>>(nodeS, e_atoms, xE, NE);
    copy_off<<<cdiv(E_ROWS * 64, TB), TB>>>(edge_feats, xE, E_ROWS, 704, 0);

    // --- MLPs ---
    run_mlp(xE, E_ROWS, 704, eW1, eg1, eb1, eW2, eg2, eb2, h, z, out_edge,
            psum, psq, sc1, sh1, sc2, sh2);
    run_mlp(new5, C5_ROWS, 320, cW1, cg1, cb1, cW2, cg2, cb2, h, z, out_c5,
            psum, psq, sc1, sh1, sc2, sh2);
    run_mlp(new6, C6_ROWS, 320, cW1, cg1, cb1, cW2, cg2, cb2, h, z, out_c6,
            psum, psq, sc1, sh1, sc2, sh2);

    (void)in_sizes;
    (void)n_in;
    (void)out_size;
}